// round 15
// baseline (speedup 1.0000x reference)
#include <cuda_runtime.h>
#include <cuda_fp16.h>
#include <cstdint>

// Problem constants
#define C_IN    256
#define S_SEQ   90
#define K_DIM   180
#define B_BATCH 4096
#define N_OUT   2086
#define MT      (B_BATCH / 128)        // 32 m-tile images (128 rows each)
#define NT      ((N_OUT + 127) / 128)  // 17 n-tile images
#define PITCH   200                    // row pitch in fp16 elems (400B, conflict-free ldmatrix)
#define TILE_E  (128 * PITCH)          // elems per 128-row tile image

#define PREP_BLOCKS ((N_OUT * K_DIM + 191) / 192)   // 1956 (scheduled FIRST)
#define CONV_BLOCKS 1024               // 4 batches per 192-thread block

// Tile images: [row][k] fp16, pitch 200. k in [180,200) stays ZERO (zero-init,
// never written); the GEMM consumes k in [0,192).
__device__ __align__(16) __half g_Ahi[MT * TILE_E];
__device__ __align__(16) __half g_Bhi[NT * TILE_E];

__device__ __forceinline__ float ex2f(float x) {
    float r;
    asm("ex2.approx.f32 %0, %1;" : "=f"(r) : "f"(x));
    return r;
}

// ---------------------------------------------------------------------------
// conv+attn fused (R12 shape, 7-blocks/SM residency): blocks [0, PREP_BLOCKS)
// do prep_b (first, so trivial work doesn't extend the tail); blocks
// [PREP_BLOCKS, PREP_BLOCKS+1024) own 4 batches each: barrier-free 256-channel
// conv stream, one barrier, ex2-softmax tail.
// __launch_bounds__(192,7) caps regs at 48 -> 1344 resident threads/SM ->
// all 196K conv threads fit in ONE wave (no ragged DRAM tail).
// ---------------------------------------------------------------------------
__global__ __launch_bounds__(192, 7) void conv_attn_kernel(
    const float* __restrict__ x, const float* __restrict__ conv_w,
    const float* __restrict__ fc_w,
    const float* __restrict__ bn_gamma, const float* __restrict__ bn_beta,
    const float* __restrict__ bn_mean,  const float* __restrict__ bn_var,
    const float* __restrict__ in_proj_w, const float* __restrict__ in_proj_b,
    const float* __restrict__ out_proj_w, const float* __restrict__ out_proj_b)
{
    // ---- prep_b blocks (first in grid) ----
    if (blockIdx.x < PREP_BLOCKS) {
        int i = blockIdx.x * 192 + threadIdx.x;
        if (i < N_OUT * K_DIM) {
            int n = i / K_DIM;
            int k = i - n * K_DIM;
            size_t idx = (size_t)(n >> 7) * TILE_E + (n & 127) * PITCH + k;
            g_Bhi[idx] = __float2half(fc_w[i]);
        }
        return;
    }

    __shared__ float2 sw[C_IN];        // (w0[c], w1[c])
    __shared__ float4 kv[4][S_SEQ];    // (k0, k1, v0, v1) per batch slot

    const int tid = threadIdx.x;
    const int bb  = tid / 48;          // 0..3
    const int u   = tid - bb * 48;     // 0..47 (u<45 active)
    const int b   = (blockIdx.x - PREP_BLOCKS) * 4 + bb;

    for (int i = tid; i < C_IN; i += 192)
        sw[i] = make_float2(conv_w[i], conv_w[C_IN + i]);
    __syncthreads();

    // ---- Phase 1: barrier-free conv stream ----
    float a00 = 0.f, a01 = 0.f, a10 = 0.f, a11 = 0.f;
    if (u < 45) {
        const float* xb = x + (size_t)b * (C_IN * S_SEQ);
#pragma unroll 16
        for (int c = 0; c < C_IN; ++c) {
            float2 xv = __ldg((const float2*)(xb + c * S_SEQ) + u);
            float2 w  = sw[c];
            a00 = fmaf(w.x, xv.x, a00);
            a01 = fmaf(w.x, xv.y, a01);
            a10 = fmaf(w.y, xv.x, a10);
            a11 = fmaf(w.y, xv.y, a11);
        }
    }

    // ---- Phase 2: BN + QKV into smem (q kept in regs) ----
    float q0a = 0.f, q1a = 0.f, q0b = 0.f, q1b = 0.f;
    if (u < 45) {
        const float s0 = __ldg(bn_gamma)     * rsqrtf(__ldg(bn_var)     + 1e-5f);
        const float s1 = __ldg(bn_gamma + 1) * rsqrtf(__ldg(bn_var + 1) + 1e-5f);
        const float sh0 = __ldg(bn_beta)     - __ldg(bn_mean)     * s0;
        const float sh1 = __ldg(bn_beta + 1) - __ldg(bn_mean + 1) * s1;
        const float w0 = __ldg(in_proj_w + 0),  w1 = __ldg(in_proj_w + 1);
        const float w2 = __ldg(in_proj_w + 2),  w3 = __ldg(in_proj_w + 3);
        const float w4 = __ldg(in_proj_w + 4),  w5 = __ldg(in_proj_w + 5);
        const float w6 = __ldg(in_proj_w + 6),  w7 = __ldg(in_proj_w + 7);
        const float w8 = __ldg(in_proj_w + 8),  w9 = __ldg(in_proj_w + 9);
        const float wa = __ldg(in_proj_w + 10), wb = __ldg(in_proj_w + 11);
        const float b0 = __ldg(in_proj_b + 0), b1 = __ldg(in_proj_b + 1);
        const float b2 = __ldg(in_proj_b + 2), b3 = __ldg(in_proj_b + 3);
        const float b4 = __ldg(in_proj_b + 4), b5 = __ldg(in_proj_b + 5);
        const float L2E = 1.44269504f;

        float y0 = fmaf(a00, s0, sh0), y1 = fmaf(a10, s1, sh1);
        q0a = L2E * fmaf(y0, w0, fmaf(y1, w1, b0));
        q1a = L2E * fmaf(y0, w2, fmaf(y1, w3, b1));
        kv[bb][2 * u] = make_float4(
            fmaf(y0, w4, fmaf(y1, w5, b2)), fmaf(y0, w6, fmaf(y1, w7, b3)),
            fmaf(y0, w8, fmaf(y1, w9, b4)), fmaf(y0, wa, fmaf(y1, wb, b5)));
        y0 = fmaf(a01, s0, sh0); y1 = fmaf(a11, s1, sh1);
        q0b = L2E * fmaf(y0, w0, fmaf(y1, w1, b0));
        q1b = L2E * fmaf(y0, w2, fmaf(y1, w3, b1));
        kv[bb][2 * u + 1] = make_float4(
            fmaf(y0, w4, fmaf(y1, w5, b2)), fmaf(y0, w6, fmaf(y1, w7, b3)),
            fmaf(y0, w8, fmaf(y1, w9, b4)), fmaf(y0, wa, fmaf(y1, wb, b5)));
    }
    __syncthreads();

    // ---- Phase 3: softmax (unshifted, exact via ex2) + out_proj + store ----
    if (u < 45) {
        float da0 = 0.f, na0 = 0.f, da1 = 0.f, na1 = 0.f;
        float db0 = 0.f, nb0 = 0.f, db1 = 0.f, nb1 = 0.f;
#pragma unroll 6
        for (int j = 0; j < S_SEQ; ++j) {
            float4 kvj = kv[bb][j];
            float ea0 = ex2f(q0a * kvj.x);
            float ea1 = ex2f(q1a * kvj.y);
            float eb0 = ex2f(q0b * kvj.x);
            float eb1 = ex2f(q1b * kvj.y);
            da0 += ea0; na0 = fmaf(ea0, kvj.z, na0);
            da1 += ea1; na1 = fmaf(ea1, kvj.w, na1);
            db0 += eb0; nb0 = fmaf(eb0, kvj.z, nb0);
            db1 += eb1; nb1 = fmaf(eb1, kvj.w, nb1);
        }
        const float p0 = __ldg(out_proj_w + 0), p1 = __ldg(out_proj_w + 1);
        const float p2 = __ldg(out_proj_w + 2), p3 = __ldg(out_proj_w + 3);
        const float pb0 = __ldg(out_proj_b), pb1 = __ldg(out_proj_b + 1);

        float oa0 = na0 / da0, oa1 = na1 / da1;
        float ob0 = nb0 / db0, ob1 = nb1 / db1;
        float fa0 = fmaf(oa0, p0, fmaf(oa1, p1, pb0));
        float fa1 = fmaf(oa0, p2, fmaf(oa1, p3, pb1));
        float fb0v = fmaf(ob0, p0, fmaf(ob1, p1, pb0));
        float fb1v = fmaf(ob0, p2, fmaf(ob1, p3, pb1));

        size_t base = (size_t)(b >> 7) * TILE_E + (size_t)(b & 127) * PITCH;
        g_Ahi[base + 2 * u]             = __float2half(fa0);
        g_Ahi[base + S_SEQ + 2 * u]     = __float2half(fa1);
        g_Ahi[base + 2 * u + 1]         = __float2half(fb0v);
        g_Ahi[base + S_SEQ + 2 * u + 1] = __float2half(fb1v);
    }
}

// ---------------------------------------------------------------------------
// FC GEMM (R12 proven, 19.3us measured): fp16 mma m16n8k16, fp32 accum,
// B-tile reuse over a 128-row m-sweep. Grid (17, 32), 256 threads,
// 102.4KB smem, 2 CTAs/SM.
// ---------------------------------------------------------------------------
#define OFF_A0 0          // 25600 B (64 rows x 400B)
#define OFF_A1 25600      // 25600 B
#define OFF_B  51200      // 51200 B (128 rows x 400B)
#define SMEM_FC 102400

__device__ __forceinline__ uint32_t smem_u32(const void* p) {
    uint32_t a;
    asm("{ .reg .u64 t; cvta.to.shared.u64 t, %1; cvt.u32.u64 %0, t; }"
        : "=r"(a) : "l"(p));
    return a;
}

#define CP16(dst, src)                                                         \
    asm volatile("cp.async.cg.shared.global [%0], [%1], 16;"                   \
                 :: "r"(dst), "l"(src))

#define LDSM4(r, addr)                                                         \
    asm volatile("ldmatrix.sync.aligned.m8n8.x4.shared.b16 {%0,%1,%2,%3}, [%4];" \
                 : "=r"((r)[0]), "=r"((r)[1]), "=r"((r)[2]), "=r"((r)[3])      \
                 : "r"(addr))

#define MMA16816(c, a, b0v, b1v)                                               \
    asm volatile(                                                              \
        "mma.sync.aligned.m16n8k16.row.col.f32.f16.f16.f32 "                   \
        "{%0,%1,%2,%3}, {%4,%5,%6,%7}, {%8,%9}, {%0,%1,%2,%3};"                \
        : "+f"((c)[0]), "+f"((c)[1]), "+f"((c)[2]), "+f"((c)[3])               \
        : "r"((a)[0]), "r"((a)[1]), "r"((a)[2]), "r"((a)[3]),                  \
          "r"(b0v), "r"(b1v))

__global__ __launch_bounds__(256, 2) void fc_mma_kernel(
    const float* __restrict__ fc_b, float* __restrict__ out)
{
    extern __shared__ char sm[];
    const uint32_t sb = smem_u32(sm);
    const int tid = threadIdx.x;
    const int wid = tid >> 5;
    const int l   = tid & 31;
    const int nt  = blockIdx.x;          // 0..16
    const int mg2 = blockIdx.y;          // 0..31 (one 128-row A image)
    const int n0  = nt * 128;

    // Stage: group 0 = A half0 + B; group 1 = A half1
    {
        const float4* gA = (const float4*)(g_Ahi + (size_t)mg2 * TILE_E);
        const float4* gB = (const float4*)(g_Bhi + (size_t)nt * TILE_E);
        for (int i = tid; i < 1600; i += 256)
            CP16(sb + OFF_A0 + i * 16, gA + i);
        for (int i = tid; i < 3200; i += 256)
            CP16(sb + OFF_B + i * 16, gB + i);
        asm volatile("cp.async.commit_group;" ::: "memory");
        for (int i = tid; i < 1600; i += 256)
            CP16(sb + OFF_A1 + i * 16, gA + 1600 + i);
        asm volatile("cp.async.commit_group;" ::: "memory");
    }

    const int wm = wid & 1;        // 2 x 32 m-rows
    const int wn = wid >> 1;       // 4 x 32 n-cols

    const uint32_t aoff = (uint32_t)((wm * 32 + (l & 15)) * 400 + ((l >> 4) & 1) * 16);
    const uint32_t boff = (uint32_t)((wn * 32 + (l & 7) + ((l >> 4) & 1) * 8) * 400
                                     + ((l >> 3) & 1) * 16);
    const int nvalid = N_OUT - n0;

    // bias regs (shared by both halves)
    float fb0[4], fb1[4];
#pragma unroll
    for (int nj = 0; nj < 4; ++nj) {
        int n = n0 + wn * 32 + nj * 8 + (l & 3) * 2;
        fb0[nj] = (n < N_OUT)     ? __ldg(fc_b + n)     : 0.f;
        fb1[nj] = (n + 1 < N_OUT) ? __ldg(fc_b + n + 1) : 0.f;
    }

#pragma unroll
    for (int half = 0; half < 2; ++half) {
        if (half == 0)
            asm volatile("cp.async.wait_group 1;" ::: "memory");
        else
            asm volatile("cp.async.wait_group 0;" ::: "memory");
        __syncthreads();

        const uint32_t Ab = sb + (half ? OFF_A1 : OFF_A0) + aoff;

        float acc[2][4][4];
#pragma unroll
        for (int mi = 0; mi < 2; ++mi)
#pragma unroll
            for (int nj = 0; nj < 4; ++nj)
#pragma unroll
                for (int r = 0; r < 4; ++r) acc[mi][nj][r] = 0.f;

#pragma unroll 4
        for (int ks = 0; ks < 12; ++ks) {
            const uint32_t ko = ks * 32;
            uint32_t a[2][4], bq0[4], bq1[4];
            LDSM4(a[0], Ab + ko);
            LDSM4(a[1], Ab + 6400 + ko);
            LDSM4(bq0, sb + OFF_B + boff + ko);
            LDSM4(bq1, sb + OFF_B + boff + 6400 + ko);
#pragma unroll
            for (int mi = 0; mi < 2; ++mi) {
                MMA16816(acc[mi][0], a[mi], bq0[0], bq0[1]);
                MMA16816(acc[mi][1], a[mi], bq0[2], bq0[3]);
                MMA16816(acc[mi][2], a[mi], bq1[0], bq1[1]);
                MMA16816(acc[mi][3], a[mi], bq1[2], bq1[3]);
            }
        }

        // Epilogue for this half
#pragma unroll
        for (int nj = 0; nj < 4; ++nj) {
            const int n = wn * 32 + nj * 8 + (l & 3) * 2;
            if (n < nvalid) {
#pragma unroll
                for (int mi = 0; mi < 2; ++mi) {
                    const int m = mg2 * 128 + half * 64 + wm * 32 + mi * 16 + (l >> 2);
                    float* p0 = out + (size_t)m * N_OUT + n0 + n;
                    float* p1 = out + (size_t)(m + 8) * N_OUT + n0 + n;
                    *(float2*)p0 = make_float2(acc[mi][nj][0] + fb0[nj],
                                               acc[mi][nj][1] + fb1[nj]);
                    *(float2*)p1 = make_float2(acc[mi][nj][2] + fb0[nj],
                                               acc[mi][nj][3] + fb1[nj]);
                }
            }
        }
    }
}

// ---------------------------------------------------------------------------
extern "C" void kernel_launch(void* const* d_in, const int* in_sizes, int n_in,
                              void* d_out, int out_size) {
    const float* x          = (const float*)d_in[0];
    const float* conv_w     = (const float*)d_in[1];
    const float* bn_gamma   = (const float*)d_in[2];
    const float* bn_beta    = (const float*)d_in[3];
    const float* bn_mean    = (const float*)d_in[4];
    const float* bn_var     = (const float*)d_in[5];
    const float* in_proj_w  = (const float*)d_in[6];
    const float* in_proj_b  = (const float*)d_in[7];
    const float* out_proj_w = (const float*)d_in[8];
    const float* out_proj_b = (const float*)d_in[9];
    const float* fc_w       = (const float*)d_in[10];
    const float* fc_b       = (const float*)d_in[11];
    float* out = (float*)d_out;

    cudaFuncSetAttribute(fc_mma_kernel,
                         cudaFuncAttributeMaxDynamicSharedMemorySize, SMEM_FC);

    conv_attn_kernel<<<PREP_BLOCKS + CONV_BLOCKS, 192>>>(
        x, conv_w, fc_w, bn_gamma, bn_beta, bn_mean, bn_var,
        in_proj_w, in_proj_b, out_proj_w, out_proj_b);
    fc_mma_kernel<<<dim3(NT, MT), 256, SMEM_FC>>>(fc_b, out);
}

// round 16
// speedup vs baseline: 1.0371x; 1.0371x over previous
#include <cuda_runtime.h>
#include <cuda_fp16.h>
#include <cstdint>

// Problem constants
#define C_IN    256
#define S_SEQ   90
#define K_DIM   180
#define B_BATCH 4096
#define N_OUT   2086
#define MT      (B_BATCH / 128)        // 32 m-tile images (128 rows each)
#define NT      ((N_OUT + 127) / 128)  // 17 n-tile images
#define PITCH   200                    // row pitch in fp16 elems (400B, conflict-free ldmatrix)
#define TILE_E  (128 * PITCH)          // elems per 128-row tile image

#define CONV_BLOCKS 1024               // 4 batches per 192-thread block (FIRST in grid)
#define PREP_BLOCKS ((N_OUT * K_DIM + 191) / 192)   // 1956 (LAST: fills conv's ragged tail)

// Tile images: [row][k] fp16, pitch 200. k in [180,200) stays ZERO (zero-init,
// never written); the GEMM consumes k in [0,192).
__device__ __align__(16) __half g_Ahi[MT * TILE_E];
__device__ __align__(16) __half g_Bhi[NT * TILE_E];

__device__ __forceinline__ float ex2f(float x) {
    float r;
    asm("ex2.approx.f32 %0, %1;" : "=f"(r) : "f"(x));
    return r;
}

// ---------------------------------------------------------------------------
// conv+attn fused (R12 structure + 7 blocks/SM): blocks [0,1024) own 4 batches
// each: barrier-free 256-channel conv stream, one barrier, ex2-softmax tail.
// Blocks [1024, 1024+1956): prep_b (fc_w -> fp16 B tile image) — LAST so the
// trivial work backfills the conv wave's ragged tail.
// __launch_bounds__(192,7): <=48 regs -> 1344 resident threads/SM -> all 196K
// conv threads fit one wave. Spills (if any) land in the MUFU-bound tail.
// ---------------------------------------------------------------------------
__global__ __launch_bounds__(192, 7) void conv_attn_kernel(
    const float* __restrict__ x, const float* __restrict__ conv_w,
    const float* __restrict__ fc_w,
    const float* __restrict__ bn_gamma, const float* __restrict__ bn_beta,
    const float* __restrict__ bn_mean,  const float* __restrict__ bn_var,
    const float* __restrict__ in_proj_w, const float* __restrict__ in_proj_b,
    const float* __restrict__ out_proj_w, const float* __restrict__ out_proj_b)
{
    // ---- prep_b blocks (last in grid) ----
    if (blockIdx.x >= CONV_BLOCKS) {
        int i = (blockIdx.x - CONV_BLOCKS) * 192 + threadIdx.x;
        if (i < N_OUT * K_DIM) {
            int n = i / K_DIM;
            int k = i - n * K_DIM;
            size_t idx = (size_t)(n >> 7) * TILE_E + (n & 127) * PITCH + k;
            g_Bhi[idx] = __float2half(fc_w[i]);
        }
        return;
    }

    __shared__ float2 sw[C_IN];        // (w0[c], w1[c])
    __shared__ float4 kv[4][S_SEQ];    // (k0, k1, v0, v1) per batch slot

    const int tid = threadIdx.x;
    const int bb  = tid / 48;          // 0..3
    const int u   = tid - bb * 48;     // 0..47 (u<45 active)
    const int b   = blockIdx.x * 4 + bb;

    for (int i = tid; i < C_IN; i += 192)
        sw[i] = make_float2(conv_w[i], conv_w[C_IN + i]);
    __syncthreads();

    // ---- Phase 1: barrier-free conv stream ----
    float a00 = 0.f, a01 = 0.f, a10 = 0.f, a11 = 0.f;
    if (u < 45) {
        const float* xb = x + (size_t)b * (C_IN * S_SEQ);
#pragma unroll 16
        for (int c = 0; c < C_IN; ++c) {
            float2 xv = __ldg((const float2*)(xb + c * S_SEQ) + u);
            float2 w  = sw[c];
            a00 = fmaf(w.x, xv.x, a00);
            a01 = fmaf(w.x, xv.y, a01);
            a10 = fmaf(w.y, xv.x, a10);
            a11 = fmaf(w.y, xv.y, a11);
        }
    }

    // ---- Phase 2: BN + QKV into smem (q kept in regs) ----
    float q0a = 0.f, q1a = 0.f, q0b = 0.f, q1b = 0.f;
    if (u < 45) {
        const float s0 = __ldg(bn_gamma)     * rsqrtf(__ldg(bn_var)     + 1e-5f);
        const float s1 = __ldg(bn_gamma + 1) * rsqrtf(__ldg(bn_var + 1) + 1e-5f);
        const float sh0 = __ldg(bn_beta)     - __ldg(bn_mean)     * s0;
        const float sh1 = __ldg(bn_beta + 1) - __ldg(bn_mean + 1) * s1;
        const float w0 = __ldg(in_proj_w + 0),  w1 = __ldg(in_proj_w + 1);
        const float w2 = __ldg(in_proj_w + 2),  w3 = __ldg(in_proj_w + 3);
        const float w4 = __ldg(in_proj_w + 4),  w5 = __ldg(in_proj_w + 5);
        const float w6 = __ldg(in_proj_w + 6),  w7 = __ldg(in_proj_w + 7);
        const float w8 = __ldg(in_proj_w + 8),  w9 = __ldg(in_proj_w + 9);
        const float wa = __ldg(in_proj_w + 10), wb = __ldg(in_proj_w + 11);
        const float b0 = __ldg(in_proj_b + 0), b1 = __ldg(in_proj_b + 1);
        const float b2 = __ldg(in_proj_b + 2), b3 = __ldg(in_proj_b + 3);
        const float b4 = __ldg(in_proj_b + 4), b5 = __ldg(in_proj_b + 5);
        const float L2E = 1.44269504f;

        float y0 = fmaf(a00, s0, sh0), y1 = fmaf(a10, s1, sh1);
        q0a = L2E * fmaf(y0, w0, fmaf(y1, w1, b0));
        q1a = L2E * fmaf(y0, w2, fmaf(y1, w3, b1));
        kv[bb][2 * u] = make_float4(
            fmaf(y0, w4, fmaf(y1, w5, b2)), fmaf(y0, w6, fmaf(y1, w7, b3)),
            fmaf(y0, w8, fmaf(y1, w9, b4)), fmaf(y0, wa, fmaf(y1, wb, b5)));
        y0 = fmaf(a01, s0, sh0); y1 = fmaf(a11, s1, sh1);
        q0b = L2E * fmaf(y0, w0, fmaf(y1, w1, b0));
        q1b = L2E * fmaf(y0, w2, fmaf(y1, w3, b1));
        kv[bb][2 * u + 1] = make_float4(
            fmaf(y0, w4, fmaf(y1, w5, b2)), fmaf(y0, w6, fmaf(y1, w7, b3)),
            fmaf(y0, w8, fmaf(y1, w9, b4)), fmaf(y0, wa, fmaf(y1, wb, b5)));
    }
    __syncthreads();

    // ---- Phase 3: softmax (unshifted, exact via ex2) + out_proj + store ----
    if (u < 45) {
        float da0 = 0.f, na0 = 0.f, da1 = 0.f, na1 = 0.f;
        float db0 = 0.f, nb0 = 0.f, db1 = 0.f, nb1 = 0.f;
#pragma unroll 6
        for (int j = 0; j < S_SEQ; ++j) {
            float4 kvj = kv[bb][j];
            float ea0 = ex2f(q0a * kvj.x);
            float ea1 = ex2f(q1a * kvj.y);
            float eb0 = ex2f(q0b * kvj.x);
            float eb1 = ex2f(q1b * kvj.y);
            da0 += ea0; na0 = fmaf(ea0, kvj.z, na0);
            da1 += ea1; na1 = fmaf(ea1, kvj.w, na1);
            db0 += eb0; nb0 = fmaf(eb0, kvj.z, nb0);
            db1 += eb1; nb1 = fmaf(eb1, kvj.w, nb1);
        }
        const float p0 = __ldg(out_proj_w + 0), p1 = __ldg(out_proj_w + 1);
        const float p2 = __ldg(out_proj_w + 2), p3 = __ldg(out_proj_w + 3);
        const float pb0 = __ldg(out_proj_b), pb1 = __ldg(out_proj_b + 1);

        float oa0 = na0 / da0, oa1 = na1 / da1;
        float ob0 = nb0 / db0, ob1 = nb1 / db1;
        float fa0 = fmaf(oa0, p0, fmaf(oa1, p1, pb0));
        float fa1 = fmaf(oa0, p2, fmaf(oa1, p3, pb1));
        float fb0v = fmaf(ob0, p0, fmaf(ob1, p1, pb0));
        float fb1v = fmaf(ob0, p2, fmaf(ob1, p3, pb1));

        size_t base = (size_t)(b >> 7) * TILE_E + (size_t)(b & 127) * PITCH;
        g_Ahi[base + 2 * u]             = __float2half(fa0);
        g_Ahi[base + S_SEQ + 2 * u]     = __float2half(fa1);
        g_Ahi[base + 2 * u + 1]         = __float2half(fb0v);
        g_Ahi[base + S_SEQ + 2 * u + 1] = __float2half(fb1v);
    }
}

// ---------------------------------------------------------------------------
// FC GEMM (R12 proven, 19.3us measured): fp16 mma m16n8k16, fp32 accum,
// B-tile reuse over a 128-row m-sweep. Grid (17, 32), 256 threads,
// 102.4KB smem, 2 CTAs/SM.
// ---------------------------------------------------------------------------
#define OFF_A0 0          // 25600 B (64 rows x 400B)
#define OFF_A1 25600      // 25600 B
#define OFF_B  51200      // 51200 B (128 rows x 400B)
#define SMEM_FC 102400

__device__ __forceinline__ uint32_t smem_u32(const void* p) {
    uint32_t a;
    asm("{ .reg .u64 t; cvta.to.shared.u64 t, %1; cvt.u32.u64 %0, t; }"
        : "=r"(a) : "l"(p));
    return a;
}

#define CP16(dst, src)                                                         \
    asm volatile("cp.async.cg.shared.global [%0], [%1], 16;"                   \
                 :: "r"(dst), "l"(src))

#define LDSM4(r, addr)                                                         \
    asm volatile("ldmatrix.sync.aligned.m8n8.x4.shared.b16 {%0,%1,%2,%3}, [%4];" \
                 : "=r"((r)[0]), "=r"((r)[1]), "=r"((r)[2]), "=r"((r)[3])      \
                 : "r"(addr))

#define MMA16816(c, a, b0v, b1v)                                               \
    asm volatile(                                                              \
        "mma.sync.aligned.m16n8k16.row.col.f32.f16.f16.f32 "                   \
        "{%0,%1,%2,%3}, {%4,%5,%6,%7}, {%8,%9}, {%0,%1,%2,%3};"                \
        : "+f"((c)[0]), "+f"((c)[1]), "+f"((c)[2]), "+f"((c)[3])               \
        : "r"((a)[0]), "r"((a)[1]), "r"((a)[2]), "r"((a)[3]),                  \
          "r"(b0v), "r"(b1v))

__global__ __launch_bounds__(256, 2) void fc_mma_kernel(
    const float* __restrict__ fc_b, float* __restrict__ out)
{
    extern __shared__ char sm[];
    const uint32_t sb = smem_u32(sm);
    const int tid = threadIdx.x;
    const int wid = tid >> 5;
    const int l   = tid & 31;
    const int nt  = blockIdx.x;          // 0..16
    const int mg2 = blockIdx.y;          // 0..31 (one 128-row A image)
    const int n0  = nt * 128;

    // Stage: group 0 = A half0 + B; group 1 = A half1
    {
        const float4* gA = (const float4*)(g_Ahi + (size_t)mg2 * TILE_E);
        const float4* gB = (const float4*)(g_Bhi + (size_t)nt * TILE_E);
        for (int i = tid; i < 1600; i += 256)
            CP16(sb + OFF_A0 + i * 16, gA + i);
        for (int i = tid; i < 3200; i += 256)
            CP16(sb + OFF_B + i * 16, gB + i);
        asm volatile("cp.async.commit_group;" ::: "memory");
        for (int i = tid; i < 1600; i += 256)
            CP16(sb + OFF_A1 + i * 16, gA + 1600 + i);
        asm volatile("cp.async.commit_group;" ::: "memory");
    }

    const int wm = wid & 1;        // 2 x 32 m-rows
    const int wn = wid >> 1;       // 4 x 32 n-cols

    const uint32_t aoff = (uint32_t)((wm * 32 + (l & 15)) * 400 + ((l >> 4) & 1) * 16);
    const uint32_t boff = (uint32_t)((wn * 32 + (l & 7) + ((l >> 4) & 1) * 8) * 400
                                     + ((l >> 3) & 1) * 16);
    const int nvalid = N_OUT - n0;

    // bias regs (shared by both halves)
    float fb0[4], fb1[4];
#pragma unroll
    for (int nj = 0; nj < 4; ++nj) {
        int n = n0 + wn * 32 + nj * 8 + (l & 3) * 2;
        fb0[nj] = (n < N_OUT)     ? __ldg(fc_b + n)     : 0.f;
        fb1[nj] = (n + 1 < N_OUT) ? __ldg(fc_b + n + 1) : 0.f;
    }

#pragma unroll
    for (int half = 0; half < 2; ++half) {
        if (half == 0)
            asm volatile("cp.async.wait_group 1;" ::: "memory");
        else
            asm volatile("cp.async.wait_group 0;" ::: "memory");
        __syncthreads();

        const uint32_t Ab = sb + (half ? OFF_A1 : OFF_A0) + aoff;

        float acc[2][4][4];
#pragma unroll
        for (int mi = 0; mi < 2; ++mi)
#pragma unroll
            for (int nj = 0; nj < 4; ++nj)
#pragma unroll
                for (int r = 0; r < 4; ++r) acc[mi][nj][r] = 0.f;

#pragma unroll 4
        for (int ks = 0; ks < 12; ++ks) {
            const uint32_t ko = ks * 32;
            uint32_t a[2][4], bq0[4], bq1[4];
            LDSM4(a[0], Ab + ko);
            LDSM4(a[1], Ab + 6400 + ko);
            LDSM4(bq0, sb + OFF_B + boff + ko);
            LDSM4(bq1, sb + OFF_B + boff + 6400 + ko);
#pragma unroll
            for (int mi = 0; mi < 2; ++mi) {
                MMA16816(acc[mi][0], a[mi], bq0[0], bq0[1]);
                MMA16816(acc[mi][1], a[mi], bq0[2], bq0[3]);
                MMA16816(acc[mi][2], a[mi], bq1[0], bq1[1]);
                MMA16816(acc[mi][3], a[mi], bq1[2], bq1[3]);
            }
        }

        // Epilogue for this half
#pragma unroll
        for (int nj = 0; nj < 4; ++nj) {
            const int n = wn * 32 + nj * 8 + (l & 3) * 2;
            if (n < nvalid) {
#pragma unroll
                for (int mi = 0; mi < 2; ++mi) {
                    const int m = mg2 * 128 + half * 64 + wm * 32 + mi * 16 + (l >> 2);
                    float* p0 = out + (size_t)m * N_OUT + n0 + n;
                    float* p1 = out + (size_t)(m + 8) * N_OUT + n0 + n;
                    *(float2*)p0 = make_float2(acc[mi][nj][0] + fb0[nj],
                                               acc[mi][nj][1] + fb1[nj]);
                    *(float2*)p1 = make_float2(acc[mi][nj][2] + fb0[nj],
                                               acc[mi][nj][3] + fb1[nj]);
                }
            }
        }
    }
}

// ---------------------------------------------------------------------------
extern "C" void kernel_launch(void* const* d_in, const int* in_sizes, int n_in,
                              void* d_out, int out_size) {
    const float* x          = (const float*)d_in[0];
    const float* conv_w     = (const float*)d_in[1];
    const float* bn_gamma   = (const float*)d_in[2];
    const float* bn_beta    = (const float*)d_in[3];
    const float* bn_mean    = (const float*)d_in[4];
    const float* bn_var     = (const float*)d_in[5];
    const float* in_proj_w  = (const float*)d_in[6];
    const float* in_proj_b  = (const float*)d_in[7];
    const float* out_proj_w = (const float*)d_in[8];
    const float* out_proj_b = (const float*)d_in[9];
    const float* fc_w       = (const float*)d_in[10];
    const float* fc_b       = (const float*)d_in[11];
    float* out = (float*)d_out;

    cudaFuncSetAttribute(fc_mma_kernel,
                         cudaFuncAttributeMaxDynamicSharedMemorySize, SMEM_FC);

    conv_attn_kernel<<<CONV_BLOCKS + PREP_BLOCKS, 192>>>(
        x, conv_w, fc_w, bn_gamma, bn_beta, bn_mean, bn_var,
        in_proj_w, in_proj_b, out_proj_w, out_proj_b);
    fc_mma_kernel<<<dim3(NT, MT), 256, SMEM_FC>>>(fc_b, out);
}

// round 17
// speedup vs baseline: 1.0922x; 1.0531x over previous
#include <cuda_runtime.h>
#include <cuda_fp16.h>
#include <cstdint>

// Problem constants
#define C_IN    256
#define S_SEQ   90
#define K_DIM   180
#define B_BATCH 4096
#define N_OUT   2086
#define MT      (B_BATCH / 128)        // 32 m-tile images (128 rows each)
#define NT      ((N_OUT + 127) / 128)  // 17 n-tile images
#define PITCH   200                    // row pitch in fp16 elems (400B, conflict-free ldmatrix)
#define TILE_E  (128 * PITCH)          // elems per 128-row tile image

#define CONV_BLOCKS 1024               // 4 batches per 192-thread block (FIRST in grid)
#define PREP_BLOCKS ((N_OUT * K_DIM + 191) / 192)   // 1956 (LAST: backfills conv tail)

// Tile images: [row][k] fp16, pitch 200. k in [180,200) stays ZERO (zero-init,
// never written); the GEMM consumes k in [0,192).
__device__ __align__(16) __half g_Ahi[MT * TILE_E];
__device__ __align__(16) __half g_Bhi[NT * TILE_E];

__device__ __forceinline__ float ex2f(float x) {
    float r;
    asm("ex2.approx.f32 %0, %1;" : "=f"(r) : "f"(x));
    return r;
}

// ---------------------------------------------------------------------------
// conv+attn fused (EXACT R12 winner): blocks [0,1024) own 4 batches each:
// barrier-free 256-channel conv stream, one barrier, ex2-softmax tail.
// Blocks [1024, 1024+1956): prep_b — LAST, backfilling the conv ragged tail.
// ---------------------------------------------------------------------------
__global__ __launch_bounds__(192, 6) void conv_attn_kernel(
    const float* __restrict__ x, const float* __restrict__ conv_w,
    const float* __restrict__ fc_w,
    const float* __restrict__ bn_gamma, const float* __restrict__ bn_beta,
    const float* __restrict__ bn_mean,  const float* __restrict__ bn_var,
    const float* __restrict__ in_proj_w, const float* __restrict__ in_proj_b,
    const float* __restrict__ out_proj_w, const float* __restrict__ out_proj_b)
{
    // ---- prep_b blocks (last in grid) ----
    if (blockIdx.x >= CONV_BLOCKS) {
        int i = (blockIdx.x - CONV_BLOCKS) * 192 + threadIdx.x;
        if (i < N_OUT * K_DIM) {
            int n = i / K_DIM;
            int k = i - n * K_DIM;
            size_t idx = (size_t)(n >> 7) * TILE_E + (n & 127) * PITCH + k;
            g_Bhi[idx] = __float2half(fc_w[i]);
        }
        return;
    }

    __shared__ float2 sw[C_IN];        // (w0[c], w1[c])
    __shared__ float4 kv[4][S_SEQ];    // (k0, k1, v0, v1) per batch slot

    const int tid = threadIdx.x;
    const int bb  = tid / 48;          // 0..3
    const int u   = tid - bb * 48;     // 0..47 (u<45 active)
    const int b   = blockIdx.x * 4 + bb;

    for (int i = tid; i < C_IN; i += 192)
        sw[i] = make_float2(conv_w[i], conv_w[C_IN + i]);
    __syncthreads();

    // ---- Phase 1: barrier-free conv stream ----
    float a00 = 0.f, a01 = 0.f, a10 = 0.f, a11 = 0.f;
    if (u < 45) {
        const float* xb = x + (size_t)b * (C_IN * S_SEQ);
#pragma unroll 16
        for (int c = 0; c < C_IN; ++c) {
            float2 xv = __ldg((const float2*)(xb + c * S_SEQ) + u);
            float2 w  = sw[c];
            a00 = fmaf(w.x, xv.x, a00);
            a01 = fmaf(w.x, xv.y, a01);
            a10 = fmaf(w.y, xv.x, a10);
            a11 = fmaf(w.y, xv.y, a11);
        }
    }

    // ---- Phase 2: BN + QKV into smem (q kept in regs) ----
    float q0a = 0.f, q1a = 0.f, q0b = 0.f, q1b = 0.f;
    if (u < 45) {
        const float s0 = __ldg(bn_gamma)     * rsqrtf(__ldg(bn_var)     + 1e-5f);
        const float s1 = __ldg(bn_gamma + 1) * rsqrtf(__ldg(bn_var + 1) + 1e-5f);
        const float sh0 = __ldg(bn_beta)     - __ldg(bn_mean)     * s0;
        const float sh1 = __ldg(bn_beta + 1) - __ldg(bn_mean + 1) * s1;
        const float w0 = __ldg(in_proj_w + 0),  w1 = __ldg(in_proj_w + 1);
        const float w2 = __ldg(in_proj_w + 2),  w3 = __ldg(in_proj_w + 3);
        const float w4 = __ldg(in_proj_w + 4),  w5 = __ldg(in_proj_w + 5);
        const float w6 = __ldg(in_proj_w + 6),  w7 = __ldg(in_proj_w + 7);
        const float w8 = __ldg(in_proj_w + 8),  w9 = __ldg(in_proj_w + 9);
        const float wa = __ldg(in_proj_w + 10), wb = __ldg(in_proj_w + 11);
        const float b0 = __ldg(in_proj_b + 0), b1 = __ldg(in_proj_b + 1);
        const float b2 = __ldg(in_proj_b + 2), b3 = __ldg(in_proj_b + 3);
        const float b4 = __ldg(in_proj_b + 4), b5 = __ldg(in_proj_b + 5);
        const float L2E = 1.44269504f;

        float y0 = fmaf(a00, s0, sh0), y1 = fmaf(a10, s1, sh1);
        q0a = L2E * fmaf(y0, w0, fmaf(y1, w1, b0));
        q1a = L2E * fmaf(y0, w2, fmaf(y1, w3, b1));
        kv[bb][2 * u] = make_float4(
            fmaf(y0, w4, fmaf(y1, w5, b2)), fmaf(y0, w6, fmaf(y1, w7, b3)),
            fmaf(y0, w8, fmaf(y1, w9, b4)), fmaf(y0, wa, fmaf(y1, wb, b5)));
        y0 = fmaf(a01, s0, sh0); y1 = fmaf(a11, s1, sh1);
        q0b = L2E * fmaf(y0, w0, fmaf(y1, w1, b0));
        q1b = L2E * fmaf(y0, w2, fmaf(y1, w3, b1));
        kv[bb][2 * u + 1] = make_float4(
            fmaf(y0, w4, fmaf(y1, w5, b2)), fmaf(y0, w6, fmaf(y1, w7, b3)),
            fmaf(y0, w8, fmaf(y1, w9, b4)), fmaf(y0, wa, fmaf(y1, wb, b5)));
    }
    __syncthreads();

    // ---- Phase 3: softmax (unshifted, exact via ex2) + out_proj + store ----
    if (u < 45) {
        float da0 = 0.f, na0 = 0.f, da1 = 0.f, na1 = 0.f;
        float db0 = 0.f, nb0 = 0.f, db1 = 0.f, nb1 = 0.f;
#pragma unroll 6
        for (int j = 0; j < S_SEQ; ++j) {
            float4 kvj = kv[bb][j];
            float ea0 = ex2f(q0a * kvj.x);
            float ea1 = ex2f(q1a * kvj.y);
            float eb0 = ex2f(q0b * kvj.x);
            float eb1 = ex2f(q1b * kvj.y);
            da0 += ea0; na0 = fmaf(ea0, kvj.z, na0);
            da1 += ea1; na1 = fmaf(ea1, kvj.w, na1);
            db0 += eb0; nb0 = fmaf(eb0, kvj.z, nb0);
            db1 += eb1; nb1 = fmaf(eb1, kvj.w, nb1);
        }
        const float p0 = __ldg(out_proj_w + 0), p1 = __ldg(out_proj_w + 1);
        const float p2 = __ldg(out_proj_w + 2), p3 = __ldg(out_proj_w + 3);
        const float pb0 = __ldg(out_proj_b), pb1 = __ldg(out_proj_b + 1);

        float oa0 = na0 / da0, oa1 = na1 / da1;
        float ob0 = nb0 / db0, ob1 = nb1 / db1;
        float fa0 = fmaf(oa0, p0, fmaf(oa1, p1, pb0));
        float fa1 = fmaf(oa0, p2, fmaf(oa1, p3, pb1));
        float fb0v = fmaf(ob0, p0, fmaf(ob1, p1, pb0));
        float fb1v = fmaf(ob0, p2, fmaf(ob1, p3, pb1));

        size_t base = (size_t)(b >> 7) * TILE_E + (size_t)(b & 127) * PITCH;
        g_Ahi[base + 2 * u]             = __float2half(fa0);
        g_Ahi[base + S_SEQ + 2 * u]     = __float2half(fa1);
        g_Ahi[base + 2 * u + 1]         = __float2half(fb0v);
        g_Ahi[base + S_SEQ + 2 * u + 1] = __float2half(fb1v);
    }
}

// ---------------------------------------------------------------------------
// FC GEMM: fp16 mma m16n8k16, fp32 accum. FUSED-HALVES k-loop:
// per k-step, load A frags for both 64-row halves (4 LDSM) + B frags ONCE
// (2 LDSM, reused) -> 16 independent MMAs per warp per k-step (2x ILP of R12),
// single staging wait, no mid-kernel barrier.
// Grid (17, 32), 256 threads, 102.4KB smem, 2 CTAs/SM (128-reg cap).
// ---------------------------------------------------------------------------
#define OFF_A  0          // 51200 B (128 rows x 400B)
#define OFF_B  51200      // 51200 B (128 rows x 400B)
#define SMEM_FC 102400

__device__ __forceinline__ uint32_t smem_u32(const void* p) {
    uint32_t a;
    asm("{ .reg .u64 t; cvta.to.shared.u64 t, %1; cvt.u32.u64 %0, t; }"
        : "=r"(a) : "l"(p));
    return a;
}

#define CP16(dst, src)                                                         \
    asm volatile("cp.async.cg.shared.global [%0], [%1], 16;"                   \
                 :: "r"(dst), "l"(src))

#define LDSM4(r, addr)                                                         \
    asm volatile("ldmatrix.sync.aligned.m8n8.x4.shared.b16 {%0,%1,%2,%3}, [%4];" \
                 : "=r"((r)[0]), "=r"((r)[1]), "=r"((r)[2]), "=r"((r)[3])      \
                 : "r"(addr))

#define MMA16816(c, a, b0v, b1v)                                               \
    asm volatile(                                                              \
        "mma.sync.aligned.m16n8k16.row.col.f32.f16.f16.f32 "                   \
        "{%0,%1,%2,%3}, {%4,%5,%6,%7}, {%8,%9}, {%0,%1,%2,%3};"                \
        : "+f"((c)[0]), "+f"((c)[1]), "+f"((c)[2]), "+f"((c)[3])               \
        : "r"((a)[0]), "r"((a)[1]), "r"((a)[2]), "r"((a)[3]),                  \
          "r"(b0v), "r"(b1v))

__global__ __launch_bounds__(256, 2) void fc_mma_kernel(
    const float* __restrict__ fc_b, float* __restrict__ out)
{
    extern __shared__ char sm[];
    const uint32_t sb = smem_u32(sm);
    const int tid = threadIdx.x;
    const int wid = tid >> 5;
    const int l   = tid & 31;
    const int nt  = blockIdx.x;          // 0..16
    const int mg2 = blockIdx.y;          // 0..31 (one 128-row A image)
    const int n0  = nt * 128;

    // Stage full A image + B tile, one group
    {
        const float4* gA = (const float4*)(g_Ahi + (size_t)mg2 * TILE_E);
        const float4* gB = (const float4*)(g_Bhi + (size_t)nt * TILE_E);
        for (int i = tid; i < 3200; i += 256) {
            CP16(sb + OFF_A + i * 16, gA + i);
            CP16(sb + OFF_B + i * 16, gB + i);
        }
        asm volatile("cp.async.commit_group;" ::: "memory");
    }

    const int wm = wid & 1;        // 2 x 32 m-rows (within each 64-row half)
    const int wn = wid >> 1;       // 4 x 32 n-cols

    const uint32_t aoff = (uint32_t)((wm * 32 + (l & 15)) * 400 + ((l >> 4) & 1) * 16);
    const uint32_t boff = (uint32_t)((wn * 32 + (l & 7) + ((l >> 4) & 1) * 8) * 400
                                     + ((l >> 3) & 1) * 16);
    const int nvalid = N_OUT - n0;

    // bias regs
    float fb0[4], fb1[4];
#pragma unroll
    for (int nj = 0; nj < 4; ++nj) {
        int n = n0 + wn * 32 + nj * 8 + (l & 3) * 2;
        fb0[nj] = (n < N_OUT)     ? __ldg(fc_b + n)     : 0.f;
        fb1[nj] = (n + 1 < N_OUT) ? __ldg(fc_b + n + 1) : 0.f;
    }

    // acc[h][mi][nj][4]: h = 64-row half
    float acc[2][2][4][4];
#pragma unroll
    for (int h = 0; h < 2; ++h)
#pragma unroll
        for (int mi = 0; mi < 2; ++mi)
#pragma unroll
            for (int nj = 0; nj < 4; ++nj)
#pragma unroll
                for (int r = 0; r < 4; ++r) acc[h][mi][nj][r] = 0.f;

    asm volatile("cp.async.wait_group 0;" ::: "memory");
    __syncthreads();

    const uint32_t Ab = sb + OFF_A + aoff;
    const uint32_t Bb = sb + OFF_B + boff;

#pragma unroll 2
    for (int ks = 0; ks < 12; ++ks) {
        const uint32_t ko = ks * 32;
        uint32_t a0[2][4], a1[2][4], bq0[4], bq1[4];
        LDSM4(a0[0], Ab + ko);                 // half0 rows [wm*32, +16)
        LDSM4(a0[1], Ab + 6400 + ko);          // half0 rows [wm*32+16, +32)
        LDSM4(a1[0], Ab + 25600 + ko);         // half1 (+64 rows)
        LDSM4(a1[1], Ab + 25600 + 6400 + ko);
        LDSM4(bq0, Bb + ko);                   // n [wn*32, +16)
        LDSM4(bq1, Bb + 6400 + ko);            // n [wn*32+16, +32)
#pragma unroll
        for (int mi = 0; mi < 2; ++mi) {
            MMA16816(acc[0][mi][0], a0[mi], bq0[0], bq0[1]);
            MMA16816(acc[0][mi][1], a0[mi], bq0[2], bq0[3]);
            MMA16816(acc[0][mi][2], a0[mi], bq1[0], bq1[1]);
            MMA16816(acc[0][mi][3], a0[mi], bq1[2], bq1[3]);
            MMA16816(acc[1][mi][0], a1[mi], bq0[0], bq0[1]);
            MMA16816(acc[1][mi][1], a1[mi], bq0[2], bq0[3]);
            MMA16816(acc[1][mi][2], a1[mi], bq1[0], bq1[1]);
            MMA16816(acc[1][mi][3], a1[mi], bq1[2], bq1[3]);
        }
    }

    // Epilogue: both halves
#pragma unroll
    for (int h = 0; h < 2; ++h) {
#pragma unroll
        for (int nj = 0; nj < 4; ++nj) {
            const int n = wn * 32 + nj * 8 + (l & 3) * 2;
            if (n < nvalid) {
#pragma unroll
                for (int mi = 0; mi < 2; ++mi) {
                    const int m = mg2 * 128 + h * 64 + wm * 32 + mi * 16 + (l >> 2);
                    float* p0 = out + (size_t)m * N_OUT + n0 + n;
                    float* p1 = out + (size_t)(m + 8) * N_OUT + n0 + n;
                    *(float2*)p0 = make_float2(acc[h][mi][nj][0] + fb0[nj],
                                               acc[h][mi][nj][1] + fb1[nj]);
                    *(float2*)p1 = make_float2(acc[h][mi][nj][2] + fb0[nj],
                                               acc[h][mi][nj][3] + fb1[nj]);
                }
            }
        }
    }
}

// ---------------------------------------------------------------------------
extern "C" void kernel_launch(void* const* d_in, const int* in_sizes, int n_in,
                              void* d_out, int out_size) {
    const float* x          = (const float*)d_in[0];
    const float* conv_w     = (const float*)d_in[1];
    const float* bn_gamma   = (const float*)d_in[2];
    const float* bn_beta    = (const float*)d_in[3];
    const float* bn_mean    = (const float*)d_in[4];
    const float* bn_var     = (const float*)d_in[5];
    const float* in_proj_w  = (const float*)d_in[6];
    const float* in_proj_b  = (const float*)d_in[7];
    const float* out_proj_w = (const float*)d_in[8];
    const float* out_proj_b = (const float*)d_in[9];
    const float* fc_w       = (const float*)d_in[10];
    const float* fc_b       = (const float*)d_in[11];
    float* out = (float*)d_out;

    cudaFuncSetAttribute(fc_mma_kernel,
                         cudaFuncAttributeMaxDynamicSharedMemorySize, SMEM_FC);

    conv_attn_kernel<<<CONV_BLOCKS + PREP_BLOCKS, 192>>>(
        x, conv_w, fc_w, bn_gamma, bn_beta, bn_mean, bn_var,
        in_proj_w, in_proj_b, out_proj_w, out_proj_b);
    fc_mma_kernel<<<dim3(NT, MT), 256, SMEM_FC>>>(fc_b, out);
}